// round 4
// baseline (speedup 1.0000x reference)
#include <cuda_runtime.h>
#include <math.h>

#define Bb 16
#define Hh 1024
#define Tt 4096
#define CD 8
#define CS 1024

static constexpr size_t OUT_N   = (size_t)Bb * Hh * Tt;          // 67108864
static constexpr size_t CL_OFF  = OUT_N;                          // 67108864
static constexpr size_t CBL_OFF = OUT_N + 1;                      // 67108865
static constexpr size_t IDX_OFF = OUT_N + 2;                      // 67108866
static constexpr size_t PROJ_OFF = IDX_OFF + (size_t)Bb * Tt;     // 67174402
static constexpr size_t PROJ_N  = (size_t)Bb * CD * Tt;           // 524288

__device__ float g_quant[(size_t)Bb * CD * Tt];   // quant scratch [B][CD][T]
__device__ float g_partial[256];                  // per-block loss partials

// ---- packed f32x2 helpers (FFMA2 path: only reachable via PTX) ----
static __device__ __forceinline__ unsigned long long pk2(float lo, float hi) {
    unsigned long long r;
    asm("mov.b64 %0, {%1, %2};" : "=l"(r) : "f"(lo), "f"(hi));
    return r;
}
static __device__ __forceinline__ void upk2(unsigned long long v, float &lo, float &hi) {
    asm("mov.b64 {%0, %1}, %2;" : "=f"(lo), "=f"(hi) : "l"(v));
}
static __device__ __forceinline__ unsigned long long f2(unsigned long long a,
                                                        unsigned long long b,
                                                        unsigned long long c) {
    unsigned long long d;
    asm("fma.rn.f32x2 %0, %1, %2, %3;" : "=l"(d) : "l"(a), "l"(b), "l"(c));
    return d;
}
static __device__ __forceinline__ unsigned long long add2(unsigned long long a,
                                                          unsigned long long b) {
    unsigned long long d;
    asm("add.rn.f32x2 %0, %1, %2;" : "=l"(d) : "l"(a), "l"(b));
    return d;
}

// =====================================================================
// K1: in-proj + NN search + proj/indices/quant/loss-partials
// grid 256 = (b, t-chunk of 256), block 256 threads (1 token / thread)
// smem layout (floats):
//   wt    [0      , 8192 )  transposed in_proj_w: wt[h*8+d]
//   cbpf  [8192   , 16384)  normalized codebook, pair-interleaved:
//                           cbpf[p*16 + d*2 + (j&1)] = cbn[j][d], p=j>>1
//   cseed [16384  , 17408)  0.5*||cbn_j||^2, pair-interleaved
//   cbraw [17408  , 25600)  raw codebook rows
//   inb   [25600  , 25608)  in_proj_b
//   red   [25608  , 25864)  loss reduction
// =====================================================================
__global__ void __launch_bounds__(256, 2) vq_k1(
    const float* __restrict__ hidden,
    const float* __restrict__ w_in,
    const float* __restrict__ b_in,
    const float* __restrict__ codebook,
    float* __restrict__ out)
{
    extern __shared__ float sm[];
    float* wt    = sm;
    float* cbpf  = sm + 8192;
    float* cseed = sm + 16384;
    float* cbraw = sm + 17408;
    float* inb   = sm + 25600;
    float* red   = sm + 25608;

    const int tid = threadIdx.x;
    const int blk = blockIdx.x;
    const int b   = blk >> 4;
    const int t0  = (blk & 15) << 8;

    // stage weights: transpose in_proj_w [CD][H] -> wt[h*8+d]
    for (int i = tid; i < CD * Hh; i += 256) {
        int d = i >> 10, h = i & 1023;
        wt[h * 8 + d] = w_in[i];
    }
    // raw codebook
    for (int i = tid; i < CS * CD; i += 256) cbraw[i] = codebook[i];
    if (tid < 8) inb[tid] = b_in[tid];
    __syncthreads();

    // normalize codebook into pair-interleaved layout
    for (int j = tid; j < CS; j += 256) {
        float c[8]; float n2 = 0.f;
#pragma unroll
        for (int d = 0; d < 8; d++) { c[d] = cbraw[j * 8 + d]; n2 += c[d] * c[d]; }
        float r = 1.0f / fmaxf(sqrtf(n2), 1e-12f);
        float cn2 = 0.f;
#pragma unroll
        for (int d = 0; d < 8; d++) { c[d] *= r; cn2 += c[d] * c[d]; }
        int p = j >> 1, o = j & 1;
#pragma unroll
        for (int d = 0; d < 8; d++) cbpf[p * 16 + d * 2 + o] = c[d];
        cseed[p * 2 + o] = 0.5f * cn2;
    }
    __syncthreads();

    const int t = t0 + tid;
    const float* hp = hidden + (size_t)b * Hh * Tt + t;

    // ---- phase A: proj = W_in * hidden + b (packed over d-pairs) ----
    unsigned long long acc0 = 0ull, acc1 = 0ull, acc2 = 0ull, acc3 = 0ull;
#pragma unroll 4
    for (int h = 0; h < Hh; h++) {
        float x = __ldg(hp + (size_t)h * Tt);
        unsigned long long hx = pk2(x, x);
        ulonglong2 wA = *(const ulonglong2*)(wt + h * 8);
        ulonglong2 wB = *(const ulonglong2*)(wt + h * 8 + 4);
        acc0 = f2(hx, wA.x, acc0);
        acc1 = f2(hx, wA.y, acc1);
        acc2 = f2(hx, wB.x, acc2);
        acc3 = f2(hx, wB.y, acc3);
    }
    float pr[8];
    upk2(acc0, pr[0], pr[1]); upk2(acc1, pr[2], pr[3]);
    upk2(acc2, pr[4], pr[5]); upk2(acc3, pr[6], pr[7]);
#pragma unroll
    for (int d = 0; d < 8; d++) pr[d] += inb[d];

    // write proj
#pragma unroll
    for (int d = 0; d < 8; d++)
        out[PROJ_OFF + ((size_t)b * 8 + d) * Tt + t] = pr[d];

    // normalize encoding
    float l2 = 0.f;
#pragma unroll
    for (int d = 0; d < 8; d++) l2 = fmaf(pr[d], pr[d], l2);
    float rr = 1.0f / fmaxf(sqrtf(l2), 1e-12f);
    unsigned long long e2[8];
#pragma unroll
    for (int d = 0; d < 8; d++) { float e = pr[d] * rr; e2[d] = pk2(e, e); }

    // ---- phase B: NN search over 512 code-pairs (packed over codes) ----
    float best = -3.4e38f; int bi = 0;
#pragma unroll 2
    for (int p = 0; p < 512; p++) {
        unsigned long long aA = *(const unsigned long long*)(cseed + p * 2);
        unsigned long long aB = 0ull;
        ulonglong2 cA = *(const ulonglong2*)(cbpf + p * 16);
        ulonglong2 cB = *(const ulonglong2*)(cbpf + p * 16 + 4);
        ulonglong2 cC = *(const ulonglong2*)(cbpf + p * 16 + 8);
        ulonglong2 cD = *(const ulonglong2*)(cbpf + p * 16 + 12);
        aA = f2(e2[0], cA.x, aA); aB = f2(e2[1], cA.y, aB);
        aA = f2(e2[2], cB.x, aA); aB = f2(e2[3], cB.y, aB);
        aA = f2(e2[4], cC.x, aA); aB = f2(e2[5], cC.y, aB);
        aA = f2(e2[6], cD.x, aA); aB = f2(e2[7], cD.y, aB);
        unsigned long long a = add2(aA, aB);
        float s0, s1; upk2(a, s0, s1);
        if (s0 > best) { best = s0; bi = 2 * p; }
        if (s1 > best) { best = s1; bi = 2 * p + 1; }
    }

    // quant = raw codebook row
    float4 q0 = *(const float4*)(cbraw + bi * 8);
    float4 q1 = *(const float4*)(cbraw + bi * 8 + 4);
    float qq[8] = { q0.x, q0.y, q0.z, q0.w, q1.x, q1.y, q1.z, q1.w };

    float ls = 0.f;
#pragma unroll
    for (int d = 0; d < 8; d++) { float df = pr[d] - qq[d]; ls = fmaf(df, df, ls); }
#pragma unroll
    for (int d = 0; d < 8; d++)
        g_quant[((size_t)b * 8 + d) * Tt + t] = qq[d];
    out[IDX_OFF + (size_t)b * Tt + t] = (float)bi;

    // deterministic block reduction of loss
    red[tid] = ls;
    __syncthreads();
    for (int s = 128; s > 0; s >>= 1) {
        if (tid < s) red[tid] += red[tid + s];
        __syncthreads();
    }
    if (tid == 0) g_partial[blk] = red[0];
}

// =====================================================================
// K2: out = W_out * quant + b_out
// grid 256 = (b, h-chunk of 256, t-chunk of 1024), block 256 (4 tokens/thread)
// smem: qs[8192] quant tile | wdf[4096] dup weights {w,w} | bs[256] bias
// =====================================================================
__global__ void __launch_bounds__(256, 2) vq_k2(
    const float* __restrict__ w_out,
    const float* __restrict__ b_out,
    float* __restrict__ out)
{
    extern __shared__ float sm[];
    float* qs  = sm;          // 8192
    float* wdf = sm + 8192;   // 4096
    float* bs  = sm + 12288;  // 256

    const int tid = threadIdx.x;
    const int blk = blockIdx.x;
    const int b  = blk >> 4;
    const int r  = blk & 15;
    const int h0 = (r >> 2) << 8;
    const int t0 = (r & 3) << 10;

    for (int i = tid; i < 8192; i += 256) {
        int d = i >> 10, tt = i & 1023;
        qs[i] = g_quant[((size_t)b * 8 + d) * Tt + t0 + tt];
    }
    for (int i = tid; i < 2048; i += 256) {
        float w = w_out[(size_t)(h0 + (i >> 3)) * 8 + (i & 7)];
        wdf[i * 2] = w; wdf[i * 2 + 1] = w;
    }
    bs[tid] = b_out[h0 + tid];
    __syncthreads();

    const int tt0 = tid * 4;
    unsigned long long qa[8], qb[8];
#pragma unroll
    for (int d = 0; d < 8; d++) {
        qa[d] = pk2(qs[d * 1024 + tt0],     qs[d * 1024 + tt0 + 1]);
        qb[d] = pk2(qs[d * 1024 + tt0 + 2], qs[d * 1024 + tt0 + 3]);
    }

    float* ob = out + ((size_t)b * Hh + h0) * Tt + t0 + tt0;
#pragma unroll 2
    for (int hl = 0; hl < 256; hl++) {
        float bh = bs[hl];
        unsigned long long aA = pk2(bh, bh);
        unsigned long long aB = aA;
        ulonglong2 wA = *(const ulonglong2*)(wdf + hl * 16);
        ulonglong2 wB = *(const ulonglong2*)(wdf + hl * 16 + 4);
        ulonglong2 wC = *(const ulonglong2*)(wdf + hl * 16 + 8);
        ulonglong2 wD = *(const ulonglong2*)(wdf + hl * 16 + 12);
        aA = f2(qa[0], wA.x, aA); aB = f2(qb[0], wA.x, aB);
        aA = f2(qa[1], wA.y, aA); aB = f2(qb[1], wA.y, aB);
        aA = f2(qa[2], wB.x, aA); aB = f2(qb[2], wB.x, aB);
        aA = f2(qa[3], wB.y, aA); aB = f2(qb[3], wB.y, aB);
        aA = f2(qa[4], wC.x, aA); aB = f2(qb[4], wC.x, aB);
        aA = f2(qa[5], wC.y, aA); aB = f2(qb[5], wC.y, aB);
        aA = f2(qa[6], wD.x, aA); aB = f2(qb[6], wD.x, aB);
        aA = f2(qa[7], wD.y, aA); aB = f2(qb[7], wD.y, aB);
        float o0, o1, o2, o3;
        upk2(aA, o0, o1); upk2(aB, o2, o3);
        *(float4*)(ob + (size_t)hl * Tt) = make_float4(o0, o1, o2, o3);
    }
}

// =====================================================================
// K3: deterministic final loss reduction, writes both loss scalars
// =====================================================================
__global__ void vq_k3(float* __restrict__ out)
{
    __shared__ double sd[256];
    const int tid = threadIdx.x;
    sd[tid] = (double)g_partial[tid];
    __syncthreads();
    for (int s = 128; s > 0; s >>= 1) {
        if (tid < s) sd[tid] += sd[tid + s];
        __syncthreads();
    }
    if (tid == 0) {
        float loss = (float)(sd[0] / (double)PROJ_N);
        out[CL_OFF]  = loss;
        out[CBL_OFF] = loss;
    }
}

extern "C" void kernel_launch(void* const* d_in, const int* in_sizes, int n_in,
                              void* d_out, int out_size)
{
    const float* hidden = (const float*)d_in[0];
    const float* w_in   = (const float*)d_in[1];
    const float* b_in   = (const float*)d_in[2];
    const float* w_out  = (const float*)d_in[3];
    const float* b_out  = (const float*)d_in[4];
    const float* cb     = (const float*)d_in[5];
    float* out = (float*)d_out;

    const int smem1 = 25864 * 4;   // 103456 B
    const int smem2 = 12544 * 4;   // 50176 B
    cudaFuncSetAttribute(vq_k1, cudaFuncAttributeMaxDynamicSharedMemorySize, smem1);
    cudaFuncSetAttribute(vq_k2, cudaFuncAttributeMaxDynamicSharedMemorySize, smem2);

    vq_k1<<<256, 256, smem1>>>(hidden, w_in, b_in, cb, out);
    vq_k2<<<256, 256, smem2>>>(w_out, b_out, out);
    vq_k3<<<1, 256>>>(out);
}

// round 6
// speedup vs baseline: 1.4444x; 1.4444x over previous
#include <cuda_runtime.h>
#include <math.h>

#define Bb 16
#define Hh 1024
#define Tt 4096
#define CD 8
#define CS 1024
#define HS 8            // H-splits for K1a
#define HC (Hh/HS)      // 128 h per block

static constexpr size_t OUT_N   = (size_t)Bb * Hh * Tt;          // 67108864
static constexpr size_t CL_OFF  = OUT_N;
static constexpr size_t CBL_OFF = OUT_N + 1;
static constexpr size_t IDX_OFF = OUT_N + 2;
static constexpr size_t PROJ_OFF = IDX_OFF + (size_t)Bb * Tt;
static constexpr size_t PROJ_N  = (size_t)Bb * CD * Tt;          // 524288

__device__ float g_pp[(size_t)HS * Bb * CD * Tt];  // partial proj [hs][b][d][t] 16.8MB
__device__ float g_quant[(size_t)Bb * CD * Tt];    // quant scratch [B][CD][T]
__device__ float g_partial[256];                   // per-block loss partials

// ---- packed f32x2 helpers ----
static __device__ __forceinline__ unsigned long long pk2(float lo, float hi) {
    unsigned long long r;
    asm("mov.b64 %0, {%1, %2};" : "=l"(r) : "f"(lo), "f"(hi));
    return r;
}
static __device__ __forceinline__ void upk2(unsigned long long v, float &lo, float &hi) {
    asm("mov.b64 {%0, %1}, %2;" : "=f"(lo), "=f"(hi) : "l"(v));
}
static __device__ __forceinline__ unsigned long long f2(unsigned long long a,
                                                        unsigned long long b,
                                                        unsigned long long c) {
    unsigned long long d;
    asm("fma.rn.f32x2 %0, %1, %2, %3;" : "=l"(d) : "l"(a), "l"(b), "l"(c));
    return d;
}
static __device__ __forceinline__ unsigned long long add2(unsigned long long a,
                                                          unsigned long long b) {
    unsigned long long d;
    asm("add.rn.f32x2 %0, %1, %2;" : "=l"(d) : "l"(a), "l"(b));
    return d;
}

// =====================================================================
// K1a: partial in-proj GEMV.
// grid 512 = b(16) x hs(8) x tc(4). block 256 threads, 4 tokens/thread
// (float4 loads), H=128 per block. Writes partials to g_pp.
// =====================================================================
__global__ void __launch_bounds__(256) vq_k1a(
    const float* __restrict__ hidden,
    const float* __restrict__ w_in)
{
    __shared__ float wdup[HC * CD * 2];   // 8KB: pk2-ready duplicated weights

    const int tid = threadIdx.x;
    const int blk = blockIdx.x;
    const int b   = blk >> 5;
    const int hs  = (blk >> 2) & 7;
    const int tc  = blk & 3;
    const int h0  = hs * HC;

    // stage duplicated weights: wdup[(h*8+d)*2 + {0,1}] = w_in[d*H + h0+h]
    for (int i = tid; i < HC * CD; i += 256) {
        int h = i >> 3, d = i & 7;
        float w = w_in[(size_t)d * Hh + h0 + h];
        wdup[i * 2] = w; wdup[i * 2 + 1] = w;
    }
    __syncthreads();

    const int tbase = tc * 1024 + tid * 4;
    const float* hp = hidden + (size_t)b * Hh * Tt + (size_t)h0 * Tt + tbase;

    unsigned long long aA[8], aB[8];
#pragma unroll
    for (int d = 0; d < 8; d++) { aA[d] = 0ull; aB[d] = 0ull; }

#pragma unroll 8
    for (int h = 0; h < HC; h++) {
        float4 xv = *(const float4*)(hp + (size_t)h * Tt);
        unsigned long long xlo = pk2(xv.x, xv.y);
        unsigned long long xhi = pk2(xv.z, xv.w);
        ulonglong2 w01 = *(const ulonglong2*)(wdup + h * 16);
        ulonglong2 w23 = *(const ulonglong2*)(wdup + h * 16 + 4);
        ulonglong2 w45 = *(const ulonglong2*)(wdup + h * 16 + 8);
        ulonglong2 w67 = *(const ulonglong2*)(wdup + h * 16 + 12);
        aA[0] = f2(xlo, w01.x, aA[0]); aB[0] = f2(xhi, w01.x, aB[0]);
        aA[1] = f2(xlo, w01.y, aA[1]); aB[1] = f2(xhi, w01.y, aB[1]);
        aA[2] = f2(xlo, w23.x, aA[2]); aB[2] = f2(xhi, w23.x, aB[2]);
        aA[3] = f2(xlo, w23.y, aA[3]); aB[3] = f2(xhi, w23.y, aB[3]);
        aA[4] = f2(xlo, w45.x, aA[4]); aB[4] = f2(xhi, w45.x, aB[4]);
        aA[5] = f2(xlo, w45.y, aA[5]); aB[5] = f2(xhi, w45.y, aB[5]);
        aA[6] = f2(xlo, w67.x, aA[6]); aB[6] = f2(xhi, w67.x, aB[6]);
        aA[7] = f2(xlo, w67.y, aA[7]); aB[7] = f2(xhi, w67.y, aB[7]);
    }

#pragma unroll
    for (int d = 0; d < 8; d++) {
        float p0, p1, p2, p3;
        upk2(aA[d], p0, p1); upk2(aB[d], p2, p3);
        size_t off = ((((size_t)hs * Bb + b) * CD + d) * Tt) + tbase;
        *(float4*)(g_pp + off) = make_float4(p0, p1, p2, p3);
    }
}

// =====================================================================
// K1b: reduce partials + bias, NN search, proj/indices/quant/loss
// grid 256 = (b, t-chunk of 256), block 256 (1 token/thread)
// =====================================================================
__global__ void __launch_bounds__(256, 2) vq_k1b(
    const float* __restrict__ b_in,
    const float* __restrict__ codebook,
    float* __restrict__ out)
{
    extern __shared__ float sm[];
    float* cbpf  = sm;           // 8192
    float* cseed = sm + 8192;    // 1024
    float* cbraw = sm + 9216;    // 8192
    float* inb   = sm + 17408;   // 8
    float* red   = sm + 17416;   // 256

    const int tid = threadIdx.x;
    const int blk = blockIdx.x;
    const int b   = blk >> 4;
    const int t0  = (blk & 15) << 8;

    for (int i = tid; i < CS * CD; i += 256) cbraw[i] = codebook[i];
    if (tid < 8) inb[tid] = b_in[tid];
    __syncthreads();

    for (int j = tid; j < CS; j += 256) {
        float c[8]; float n2 = 0.f;
#pragma unroll
        for (int d = 0; d < 8; d++) { c[d] = cbraw[j * 8 + d]; n2 += c[d] * c[d]; }
        float r = 1.0f / fmaxf(sqrtf(n2), 1e-12f);
        float cn2 = 0.f;
#pragma unroll
        for (int d = 0; d < 8; d++) { c[d] *= r; cn2 += c[d] * c[d]; }
        int p = j >> 1, o = j & 1;
#pragma unroll
        for (int d = 0; d < 8; d++) cbpf[p * 16 + d * 2 + o] = c[d];
        cseed[p * 2 + o] = 0.5f * cn2;
    }
    __syncthreads();

    const int t = t0 + tid;

    // reduce HS partials in fixed order (deterministic)
    float pr[8];
#pragma unroll
    for (int d = 0; d < 8; d++) {
        float s = inb[d];
#pragma unroll
        for (int hs = 0; hs < HS; hs++)
            s += g_pp[((((size_t)hs * Bb + b) * CD + d) * Tt) + t];
        pr[d] = s;
    }

#pragma unroll
    for (int d = 0; d < 8; d++)
        out[PROJ_OFF + ((size_t)b * 8 + d) * Tt + t] = pr[d];

    float l2 = 0.f;
#pragma unroll
    for (int d = 0; d < 8; d++) l2 = fmaf(pr[d], pr[d], l2);
    float rr = 1.0f / fmaxf(sqrtf(l2), 1e-12f);
    unsigned long long e2[8];
#pragma unroll
    for (int d = 0; d < 8; d++) { float e = pr[d] * rr; e2[d] = pk2(e, e); }

    float best = -3.4e38f; int bi = 0;
#pragma unroll 2
    for (int p = 0; p < 512; p++) {
        unsigned long long sA = *(const unsigned long long*)(cseed + p * 2);
        unsigned long long sB = 0ull;
        ulonglong2 cA = *(const ulonglong2*)(cbpf + p * 16);
        ulonglong2 cB = *(const ulonglong2*)(cbpf + p * 16 + 4);
        ulonglong2 cC = *(const ulonglong2*)(cbpf + p * 16 + 8);
        ulonglong2 cD = *(const ulonglong2*)(cbpf + p * 16 + 12);
        sA = f2(e2[0], cA.x, sA); sB = f2(e2[1], cA.y, sB);
        sA = f2(e2[2], cB.x, sA); sB = f2(e2[3], cB.y, sB);
        sA = f2(e2[4], cC.x, sA); sB = f2(e2[5], cC.y, sB);
        sA = f2(e2[6], cD.x, sA); sB = f2(e2[7], cD.y, sB);
        unsigned long long a = add2(sA, sB);
        float s0, s1; upk2(a, s0, s1);
        if (s0 > best) { best = s0; bi = 2 * p; }
        if (s1 > best) { best = s1; bi = 2 * p + 1; }
    }

    float4 q0 = *(const float4*)(cbraw + bi * 8);
    float4 q1 = *(const float4*)(cbraw + bi * 8 + 4);
    float qq[8] = { q0.x, q0.y, q0.z, q0.w, q1.x, q1.y, q1.z, q1.w };

    float ls = 0.f;
#pragma unroll
    for (int d = 0; d < 8; d++) { float df = pr[d] - qq[d]; ls = fmaf(df, df, ls); }
#pragma unroll
    for (int d = 0; d < 8; d++)
        g_quant[((size_t)b * 8 + d) * Tt + t] = qq[d];
    out[IDX_OFF + (size_t)b * Tt + t] = (float)bi;

    red[tid] = ls;
    __syncthreads();
    for (int s = 128; s > 0; s >>= 1) {
        if (tid < s) red[tid] += red[tid + s];
        __syncthreads();
    }
    if (tid == 0) g_partial[blk] = red[0];
}

// =====================================================================
// K2: out = W_out * quant + b_out   (unchanged from passing R1 version)
// =====================================================================
__global__ void __launch_bounds__(256, 2) vq_k2(
    const float* __restrict__ w_out,
    const float* __restrict__ b_out,
    float* __restrict__ out)
{
    extern __shared__ float sm[];
    float* qs  = sm;          // 8192
    float* wdf = sm + 8192;   // 4096
    float* bs  = sm + 12288;  // 256

    const int tid = threadIdx.x;
    const int blk = blockIdx.x;
    const int b  = blk >> 4;
    const int r  = blk & 15;
    const int h0 = (r >> 2) << 8;
    const int t0 = (r & 3) << 10;

    for (int i = tid; i < 8192; i += 256) {
        int d = i >> 10, tt = i & 1023;
        qs[i] = g_quant[((size_t)b * 8 + d) * Tt + t0 + tt];
    }
    for (int i = tid; i < 2048; i += 256) {
        float w = w_out[(size_t)(h0 + (i >> 3)) * 8 + (i & 7)];
        wdf[i * 2] = w; wdf[i * 2 + 1] = w;
    }
    bs[tid] = b_out[h0 + tid];
    __syncthreads();

    const int tt0 = tid * 4;
    unsigned long long qa[8], qb[8];
#pragma unroll
    for (int d = 0; d < 8; d++) {
        qa[d] = pk2(qs[d * 1024 + tt0],     qs[d * 1024 + tt0 + 1]);
        qb[d] = pk2(qs[d * 1024 + tt0 + 2], qs[d * 1024 + tt0 + 3]);
    }

    float* ob = out + ((size_t)b * Hh + h0) * Tt + t0 + tt0;
#pragma unroll 2
    for (int hl = 0; hl < 256; hl++) {
        float bh = bs[hl];
        unsigned long long aA = pk2(bh, bh);
        unsigned long long aB = aA;
        ulonglong2 wA = *(const ulonglong2*)(wdf + hl * 16);
        ulonglong2 wB = *(const ulonglong2*)(wdf + hl * 16 + 4);
        ulonglong2 wC = *(const ulonglong2*)(wdf + hl * 16 + 8);
        ulonglong2 wD = *(const ulonglong2*)(wdf + hl * 16 + 12);
        aA = f2(qa[0], wA.x, aA); aB = f2(qb[0], wA.x, aB);
        aA = f2(qa[1], wA.y, aA); aB = f2(qb[1], wA.y, aB);
        aA = f2(qa[2], wB.x, aA); aB = f2(qb[2], wB.x, aB);
        aA = f2(qa[3], wB.y, aA); aB = f2(qb[3], wB.y, aB);
        aA = f2(qa[4], wC.x, aA); aB = f2(qb[4], wC.x, aB);
        aA = f2(qa[5], wC.y, aA); aB = f2(qb[5], wC.y, aB);
        aA = f2(qa[6], wD.x, aA); aB = f2(qb[6], wD.x, aB);
        aA = f2(qa[7], wD.y, aA); aB = f2(qb[7], wD.y, aB);
        float o0, o1, o2, o3;
        upk2(aA, o0, o1); upk2(aB, o2, o3);
        *(float4*)(ob + (size_t)hl * Tt) = make_float4(o0, o1, o2, o3);
    }
}

// =====================================================================
// K3: deterministic final loss reduction
// =====================================================================
__global__ void vq_k3(float* __restrict__ out)
{
    __shared__ double sd[256];
    const int tid = threadIdx.x;
    sd[tid] = (double)g_partial[tid];
    __syncthreads();
    for (int s = 128; s > 0; s >>= 1) {
        if (tid < s) sd[tid] += sd[tid + s];
        __syncthreads();
    }
    if (tid == 0) {
        float loss = (float)(sd[0] / (double)PROJ_N);
        out[CL_OFF]  = loss;
        out[CBL_OFF] = loss;
    }
}

extern "C" void kernel_launch(void* const* d_in, const int* in_sizes, int n_in,
                              void* d_out, int out_size)
{
    const float* hidden = (const float*)d_in[0];
    const float* w_in   = (const float*)d_in[1];
    const float* b_in   = (const float*)d_in[2];
    const float* w_out  = (const float*)d_in[3];
    const float* b_out  = (const float*)d_in[4];
    const float* cb     = (const float*)d_in[5];
    float* out = (float*)d_out;

    const int smem1b = 17672 * 4;  // 70688 B
    const int smem2  = 12544 * 4;  // 50176 B
    cudaFuncSetAttribute(vq_k1b, cudaFuncAttributeMaxDynamicSharedMemorySize, smem1b);
    cudaFuncSetAttribute(vq_k2,  cudaFuncAttributeMaxDynamicSharedMemorySize, smem2);

    vq_k1a<<<512, 256>>>(hidden, w_in);
    vq_k1b<<<256, 256, smem1b>>>(b_in, cb, out);
    vq_k2<<<256, 256, smem2>>>(w_out, b_out, out);
    vq_k3<<<1, 256>>>(out);
}